// round 3
// baseline (speedup 1.0000x reference)
#include <cuda_runtime.h>

// ---------------------------------------------------------------------------
// SpatioTemporalGNNLayer: out = relu(conv3x3(x,Ww)+Wb + conv3x3(agg,Bw)+Bb)
// agg[dst] = mean over incoming edges of x[src].
//
// CSR build (detect dtype -> zero -> count -> warp-scan -> fill), then one
// fused per-node kernel: gather-mean + both convs (packed f32x2 FFMA2) + relu.
// ---------------------------------------------------------------------------

#define NNODES 4096
#define NEDGES 16384
#define NODE_ELEMS 4096          // 16*16*16
#define CIN 16
#define COUT 16
#define RS 18                    // smem row stride: [pad0 | 16 px | pad0]
#define CHS (18*RS)              // 18 rows (1 pad above + 16 + 1 below) = 324
#define NMASK (NNODES - 1)

typedef unsigned long long ull;

__device__ __align__(16) int g_deg[NNODES];
__device__ int g_cur[NNODES];
__device__ int g_off[NNODES + 1];
__device__ int g_srcs[NEDGES];
__device__ int g_is64;

// ---- packed f32x2 helpers --------------------------------------------------
#define FMA2(d, a, b, c) \
    asm("fma.rn.f32x2 %0, %1, %2, %3;" : "=l"(d) : "l"(a), "l"(b), "l"(c))
#define PACK2(d, lo, hi) \
    asm("mov.b64 %0, {%1, %2};" : "=l"(d) : "f"(lo), "f"(hi))
#define UNPACK2(lo, hi, s) \
    asm("mov.b64 {%0, %1}, %2;" : "=f"(lo), "=f"(hi) : "l"(s))

// ---------------------------------------------------------------------------
// Detect int64 vs int32 edge_index: for int64 little-endian values < 4096,
// every high word is zero. 32 samples -> false positive prob ~ 4096^-32.
__global__ void detect_kernel(const int* __restrict__ ei32, int E) {
    int n = (E < 32) ? E : 32;
    int odd = (threadIdx.x < n) ? ei32[2 * threadIdx.x + 1] : 0;
    unsigned nz = __ballot_sync(0xffffffffu, odd != 0);
    if (threadIdx.x == 0) g_is64 = (nz == 0);
}

__global__ void zero_kernel() {
    int i = blockIdx.x * blockDim.x + threadIdx.x;
    if (i < NNODES) { g_deg[i] = 0; g_cur[i] = 0; }
}

__device__ __forceinline__ int load_idx(const int* ei32, int pos) {
    return g_is64 ? (ei32[2 * pos] & NMASK) : (ei32[pos] & NMASK);
}

__global__ void count_kernel(const int* __restrict__ ei32, int E) {
    int e = blockIdx.x * blockDim.x + threadIdx.x;
    if (e < E) atomicAdd(&g_deg[load_idx(ei32, E + e)], 1);
}

// exclusive scan of 4096 counters: warp-shuffle scan, 2 barriers total
__global__ void scan_kernel() {
    __shared__ int wsum[32];
    int t = threadIdx.x;            // 1024 threads, 4 items each
    int lane = t & 31, wid = t >> 5;
    int4 v = ((const int4*)g_deg)[t];
    int sum = v.x + v.y + v.z + v.w;
    int s = sum;
#pragma unroll
    for (int d = 1; d < 32; d <<= 1) {
        int n = __shfl_up_sync(0xffffffffu, s, d);
        if (lane >= d) s += n;
    }
    if (lane == 31) wsum[wid] = s;
    __syncthreads();
    if (wid == 0) {
        int ws = wsum[lane];
#pragma unroll
        for (int d = 1; d < 32; d <<= 1) {
            int n = __shfl_up_sync(0xffffffffu, ws, d);
            if (lane >= d) ws += n;
        }
        wsum[lane] = ws;
    }
    __syncthreads();
    int excl = ((wid > 0) ? wsum[wid - 1] : 0) + s - sum;
    g_off[4 * t + 0] = excl;
    g_off[4 * t + 1] = excl + v.x;
    g_off[4 * t + 2] = excl + v.x + v.y;
    g_off[4 * t + 3] = excl + v.x + v.y + v.z;
    if (t == 1023) g_off[NNODES] = wsum[31];
}

__global__ void fill_kernel(const int* __restrict__ ei32, int E) {
    int e = blockIdx.x * blockDim.x + threadIdx.x;
    if (e < E) {
        int sc = load_idx(ei32, e);
        int d  = load_idx(ei32, E + e);
        int pos = g_off[d] + atomicAdd(&g_cur[d], 1);
        g_srcs[pos] = sc;
    }
}

// ---------------------------------------------------------------------------
// One 3x3-channel contribution, 16 px of one output row, packed f32x2.
// ch points at a padded channel image: 18 rows x 18 floats,
// row layout [0 | x0..x15 | 0]; output row 'row' reads buffer rows row..row+2.
__device__ __forceinline__ void conv_accum2(const float* __restrict__ ch, int row,
                                            const float* __restrict__ w, ull* acc) {
    ull w2[9];
#pragma unroll
    for (int i = 0; i < 9; i++) { float wi = w[i]; PACK2(w2[i], wi, wi); }
#pragma unroll
    for (int r = 0; r < 3; r++) {
        const ull* p = (const ull*)(ch + (row + r) * RS);
        ull P[9];
        float f[18];
#pragma unroll
        for (int k = 0; k < 9; k++) {
            P[k] = p[k];
            UNPACK2(f[2 * k], f[2 * k + 1], P[k]);
        }
#pragma unroll
        for (int k = 0; k < 8; k++) {
            ull S; PACK2(S, f[2 * k + 1], f[2 * k + 2]);
            FMA2(acc[k], w2[3 * r + 0], P[k],     acc[k]);
            FMA2(acc[k], w2[3 * r + 1], S,        acc[k]);
            FMA2(acc[k], w2[3 * r + 2], P[k + 1], acc[k]);
        }
    }
}

__global__ __launch_bounds__(256, 2) void gnn_main_kernel(
    const float* __restrict__ x,
    const float* __restrict__ Ww, const float* __restrict__ Wbias,
    const float* __restrict__ Bw, const float* __restrict__ Bbias,
    float* __restrict__ out) {
    extern __shared__ float sm[];
    float* xs  = sm;                      // 16 * 324
    float* as  = xs + CIN * CHS;          // 16 * 324
    float* sWw = as + CIN * CHS;          // 2304
    float* sBw = sWw + 2304;              // 2304
    float* sWb = sBw + 2304;              // 16
    float* sBb = sWb + 16;                // 16

    int tid  = threadIdx.x;
    int node = blockIdx.x;

    // zero both padded image buffers (pads stay zero; data overwritten below)
    float4* z4 = (float4*)sm;
#pragma unroll
    for (int i = tid; i < (2 * CIN * CHS) / 4; i += 256)
        z4[i] = make_float4(0.f, 0.f, 0.f, 0.f);

    // stage weights
    for (int i = tid; i < 2304; i += 256) { sWw[i] = Ww[i]; sBw[i] = Bw[i]; }
    if (tid < 16) { sWb[tid] = Wbias[tid]; sBb[tid] = Bbias[tid]; }

    // gather-mean over incoming edges (register accumulate, 4 float4/thread)
    const float4* xp = (const float4*)(x + (size_t)node * NODE_ELEMS);
    float4 a[4];
#pragma unroll
    for (int k = 0; k < 4; k++) a[k] = make_float4(0.f, 0.f, 0.f, 0.f);

    int beg = g_off[node], end = g_off[node + 1];
    for (int e = beg; e < end; e++) {
        int sc = g_srcs[e] & NMASK;
        const float4* sp = (const float4*)(x + (size_t)sc * NODE_ELEMS);
#pragma unroll
        for (int k = 0; k < 4; k++) {
            float4 v = __ldg(&sp[tid + 256 * k]);
            a[k].x += v.x; a[k].y += v.y; a[k].z += v.z; a[k].w += v.w;
        }
    }
    float inv = 1.0f / (float)max(end - beg, 1);

    __syncthreads();   // zeros (pads) must be in place before data stores

    // scatter x[node] and agg into padded layout (scalar stores, offset +1)
#pragma unroll
    for (int k = 0; k < 4; k++) {
        int i4  = tid + 256 * k;          // float4 index within node block
        int ci  = i4 >> 6;                // 64 float4 per channel
        int rem = i4 & 63;
        int y   = rem >> 2;               // 4 float4 per row
        int x4  = rem & 3;
        int base = ci * CHS + (y + 1) * RS + 1 + 4 * x4;
        float4 xv = xp[i4];
        xs[base + 0] = xv.x; xs[base + 1] = xv.y;
        xs[base + 2] = xv.z; xs[base + 3] = xv.w;
        as[base + 0] = a[k].x * inv; as[base + 1] = a[k].y * inv;
        as[base + 2] = a[k].z * inv; as[base + 3] = a[k].w * inv;
    }
    __syncthreads();

    // conv phase: thread (co,row) computes 16 output pixels via f32x2
    int co  = tid >> 4;
    int row = tid & 15;
    float bias = sWb[co] + sBb[co];
    ull acc[8];
    ull bias2; PACK2(bias2, bias, bias);
#pragma unroll
    for (int k = 0; k < 8; k++) acc[k] = bias2;

#pragma unroll 1
    for (int ci = 0; ci < 16; ci++) {
        conv_accum2(xs + ci * CHS, row, sWw + (co * 16 + ci) * 9, acc);
        conv_accum2(as + ci * CHS, row, sBw + (co * 16 + ci) * 9, acc);
    }

    float o[16];
#pragma unroll
    for (int k = 0; k < 8; k++) UNPACK2(o[2 * k], o[2 * k + 1], acc[k]);

    float4* op4 = (float4*)(out + (size_t)node * NODE_ELEMS + co * 256 + row * 16);
#pragma unroll
    for (int k = 0; k < 4; k++) {
        op4[k] = make_float4(fmaxf(o[4 * k + 0], 0.f), fmaxf(o[4 * k + 1], 0.f),
                             fmaxf(o[4 * k + 2], 0.f), fmaxf(o[4 * k + 3], 0.f));
    }
}

// ---------------------------------------------------------------------------
extern "C" void kernel_launch(void* const* d_in, const int* in_sizes, int n_in,
                              void* d_out, int out_size) {
    const float* x   = (const float*)d_in[0];
    const int*   ei  = (const int*)d_in[1];   // int32 view; detect resolves dtype
    const float* Ww  = (const float*)d_in[2];
    const float* Wb  = (const float*)d_in[3];
    const float* Bw  = (const float*)d_in[4];
    const float* Bb  = (const float*)d_in[5];
    float*       out = (float*)d_out;

    int E = in_sizes[1] / 2;
    int N = in_sizes[0] / NODE_ELEMS;

    detect_kernel<<<1, 32>>>(ei, E);
    zero_kernel<<<(NNODES + 255) / 256, 256>>>();
    count_kernel<<<(E + 255) / 256, 256>>>(ei, E);
    scan_kernel<<<1, 1024>>>();
    fill_kernel<<<(E + 255) / 256, 256>>>(ei, E);

    int smem_bytes = (2 * CIN * CHS + 2 * 2304 + 32) * (int)sizeof(float); // ~60KB
    cudaFuncSetAttribute(gnn_main_kernel,
                         cudaFuncAttributeMaxDynamicSharedMemorySize, smem_bytes);
    gnn_main_kernel<<<N, 256, smem_bytes>>>(x, Ww, Wb, Bw, Bb, out);
}